// round 2
// baseline (speedup 1.0000x reference)
#include <cuda_runtime.h>
#include <math.h>

#define BB 32
#define FF 128
#define HH 256
#define NPTS 2048
#define SD 3
#define LAYERS 2
#define NE 262144
#define NN (BB*NPTS)      // 65536
#define TE 16
#define FSTRIDE 516       // 513 padded to mult of 4 (float4 loads)
#define USTRIDE 512

// ---------------- scratch (device globals; no allocation allowed) ----------
__device__ float g_h0[BB*HH];
__device__ float g_meand[NPTS];
__device__ float g_g[NPTS*HH];
__device__ float g_h[NN*HH];       // 64 MB
__device__ float g_pos[NN*SD];
__device__ float g_agg[NN*HH];     // 64 MB
__device__ float g_dpos[NN*SD];

// ---------------- zero agg + dpos -------------------------------------------
__global__ void k_zero()
{
    int i = blockIdx.x * blockDim.x + threadIdx.x;
    int stride = gridDim.x * blockDim.x;
    for (int k = i; k < NN*HH; k += stride) g_agg[k] = 0.f;
    for (int k = i; k < NN*SD; k += stride) g_dpos[k] = 0.f;
}

// ---------------- h0 = x @ W_in + b_in  [32,256] ---------------------------
__global__ void k_h0(const float* __restrict__ x, const float* __restrict__ W,
                     const float* __restrict__ b)
{
    int bi = blockIdx.x, j = threadIdx.x;
    __shared__ float xr[FF];
    if (j < FF) xr[j] = x[bi*FF + j];
    __syncthreads();
    float acc = b[j];
    #pragma unroll 4
    for (int k = 0; k < FF; k++) acc = fmaf(xr[k], W[k*HH + j], acc);
    g_h0[bi*HH + j] = acc;
}

// ---------------- mean pairwise distance per point --------------------------
__global__ void k_meand(const float* __restrict__ P)
{
    int i = blockIdx.x;
    float px = P[i*3+0], py = P[i*3+1], pz = P[i*3+2];
    float s = 0.f;
    for (int j = threadIdx.x; j < NPTS; j += 256) {
        if (j == i) continue;
        float dx = px - P[j*3+0], dy = py - P[j*3+1], dz = pz - P[j*3+2];
        s += sqrtf(dx*dx + dy*dy + dz*dz);
    }
    __shared__ float red[256];
    red[threadIdx.x] = s;
    __syncthreads();
    for (int st = 128; st > 0; st >>= 1) {
        if (threadIdx.x < st) red[threadIdx.x] += red[threadIdx.x + st];
        __syncthreads();
    }
    if (threadIdx.x == 0) g_meand[i] = red[0] / (float)(NPTS - 1);
}

// ------- g = relu(gf@Wg1+bg1)@Wg2+bg2, gf cols are all mean_d ---------------
__global__ void k_geo(const float* __restrict__ Wg1, const float* __restrict__ bg1,
                      const float* __restrict__ Wg2, const float* __restrict__ bg2)
{
    int i = blockIdx.x, j = threadIdx.x;
    __shared__ float t[FF];
    float m = g_meand[i];
    if (j < FF) {
        float ws = Wg1[j] + Wg1[FF + j] + Wg1[2*FF + j];
        t[j] = fmaxf(fmaf(m, ws, bg1[j]), 0.f);
    }
    __syncthreads();
    float acc = bg2[j];
    #pragma unroll 4
    for (int k = 0; k < FF; k++) acc = fmaf(t[k], Wg2[k*HH + j], acc);
    g_g[i*HH + j] = acc;
}

// ---------------- init node features & positions ----------------------------
__global__ void k_init(const float* __restrict__ P)
{
    int bn = blockIdx.x, j = threadIdx.x;
    int b = bn >> 11, n = bn & (NPTS - 1);
    g_h[bn*HH + j] = g_h0[b*HH + j] + g_g[n*HH + j];
    if (j < SD) g_pos[bn*SD + j] = P[n*SD + j];
}

// ---------------- message kernel: per 16-edge tile --------------------------
// m = relu([h_src; h_dst; d] @ Wm + bm); agg[dst] += m;
// coef = m @ Wp; dpos[dst] += (pos_dst - pos_src) * coef
__global__ void __launch_bounds__(256) msg_kernel(
    const int* __restrict__ src, const int* __restrict__ dst,
    const float* __restrict__ Wm, const float* __restrict__ bm,
    const float* __restrict__ Wp)
{
    __shared__ float sm[TE * FSTRIDE];       // 33024 B
    __shared__ int ssrc[TE], sdst[TE];
    __shared__ float spart[8][TE];
    int tid = threadIdx.x;
    int e0 = blockIdx.x * TE;

    if (tid < TE) { ssrc[tid] = src[e0 + tid]; sdst[tid] = dst[e0 + tid]; }
    __syncthreads();

    #pragma unroll 4
    for (int e = 0; e < TE; e++) {
        sm[e*FSTRIDE + tid]      = g_h[ssrc[e]*HH + tid];
        sm[e*FSTRIDE + HH + tid] = g_h[sdst[e]*HH + tid];
    }
    if (tid < TE) {
        int s = ssrc[tid], t = sdst[tid];
        float dx = g_pos[s*3+0] - g_pos[t*3+0];
        float dy = g_pos[s*3+1] - g_pos[t*3+1];
        float dz = g_pos[s*3+2] - g_pos[t*3+2];
        sm[tid*FSTRIDE + 512] = sqrtf(dx*dx + dy*dy + dz*dz + 1e-12f);
    }
    __syncthreads();

    float acc[TE];
    #pragma unroll
    for (int e = 0; e < TE; e++) acc[e] = 0.f;

    const float* wc = Wm + tid;              // column tid, stride HH
    for (int k4 = 0; k4 < 128; k4++) {
        float w0 = wc[(4*k4 + 0)*HH];
        float w1 = wc[(4*k4 + 1)*HH];
        float w2 = wc[(4*k4 + 2)*HH];
        float w3 = wc[(4*k4 + 3)*HH];
        #pragma unroll
        for (int e = 0; e < TE; e++) {
            float4 f = *(const float4*)(sm + e*FSTRIDE + 4*k4);
            acc[e] = fmaf(f.w, w3, fmaf(f.z, w2, fmaf(f.y, w1, fmaf(f.x, w0, acc[e]))));
        }
    }
    float wd = wc[512*HH];
    float bj = bm[tid];
    #pragma unroll
    for (int e = 0; e < TE; e++) {
        acc[e] = fmaf(sm[e*FSTRIDE + 512], wd, acc[e]);
        acc[e] = fmaxf(acc[e] + bj, 0.f);
    }

    // segment-sum of messages into agg[dst]
    #pragma unroll 4
    for (int e = 0; e < TE; e++) atomicAdd(g_agg + sdst[e]*HH + tid, acc[e]);

    // coef[e] = sum_j m[e][j] * Wp[j]  (cross-thread reduce)
    float wp = Wp[tid];
    int lane = tid & 31, wrp = tid >> 5;
    #pragma unroll
    for (int e = 0; e < TE; e++) {
        float v = acc[e] * wp;
        v += __shfl_xor_sync(0xffffffffu, v, 16);
        v += __shfl_xor_sync(0xffffffffu, v, 8);
        v += __shfl_xor_sync(0xffffffffu, v, 4);
        v += __shfl_xor_sync(0xffffffffu, v, 2);
        v += __shfl_xor_sync(0xffffffffu, v, 1);
        if (lane == 0) spart[wrp][e] = v;
    }
    __syncthreads();
    if (tid < TE) {
        float c = spart[0][tid] + spart[1][tid] + spart[2][tid] + spart[3][tid]
                + spart[4][tid] + spart[5][tid] + spart[6][tid] + spart[7][tid];
        int s = ssrc[tid], t = sdst[tid];
        atomicAdd(g_dpos + t*3+0, (g_pos[t*3+0] - g_pos[s*3+0]) * c);
        atomicAdd(g_dpos + t*3+1, (g_pos[t*3+1] - g_pos[s*3+1]) * c);
        atomicAdd(g_dpos + t*3+2, (g_pos[t*3+2] - g_pos[s*3+2]) * c);
    }
}

// ---------------- update kernel: per 16-node tile ---------------------------
// h += relu([h; agg] @ Wu + bu); pos += dpos / DEG
__global__ void __launch_bounds__(256) upd_kernel(
    const float* __restrict__ Wu, const float* __restrict__ bu)
{
    __shared__ float sm[TE * USTRIDE];       // 32768 B
    int tid = threadIdx.x;
    int n0 = blockIdx.x * TE;

    #pragma unroll 4
    for (int e = 0; e < TE; e++) {
        sm[e*USTRIDE + tid]      = g_h[(n0 + e)*HH + tid];
        sm[e*USTRIDE + HH + tid] = g_agg[(n0 + e)*HH + tid];
    }
    __syncthreads();

    float acc[TE];
    #pragma unroll
    for (int e = 0; e < TE; e++) acc[e] = 0.f;

    const float* wc = Wu + tid;
    for (int k4 = 0; k4 < 128; k4++) {
        float w0 = wc[(4*k4 + 0)*HH];
        float w1 = wc[(4*k4 + 1)*HH];
        float w2 = wc[(4*k4 + 2)*HH];
        float w3 = wc[(4*k4 + 3)*HH];
        #pragma unroll
        for (int e = 0; e < TE; e++) {
            float4 f = *(const float4*)(sm + e*USTRIDE + 4*k4);
            acc[e] = fmaf(f.w, w3, fmaf(f.z, w2, fmaf(f.y, w1, fmaf(f.x, w0, acc[e]))));
        }
    }
    float bj = bu[tid];
    #pragma unroll
    for (int e = 0; e < TE; e++)
        g_h[(n0 + e)*HH + tid] = sm[e*USTRIDE + tid] + fmaxf(acc[e] + bj, 0.f);

    if (tid < TE*SD) {
        int n = n0 + tid / 3, c = tid % 3;
        g_pos[n*3 + c] += g_dpos[n*3 + c] * 0.25f;   // 1/DEG, DEG = E/(B*N) = 4
    }
}

// ---------------- output: out[bn] = h[bn] . W_out + b_out -------------------
__global__ void k_out(const float* __restrict__ Wo, const float* __restrict__ bo,
                      float* __restrict__ out)
{
    int lane = threadIdx.x & 31;
    int node = blockIdx.x * 8 + (threadIdx.x >> 5);
    float v = 0.f;
    #pragma unroll
    for (int r = 0; r < 8; r++) {
        int j = lane + r*32;
        v = fmaf(g_h[node*HH + j], Wo[j], v);
    }
    v += __shfl_xor_sync(0xffffffffu, v, 16);
    v += __shfl_xor_sync(0xffffffffu, v, 8);
    v += __shfl_xor_sync(0xffffffffu, v, 4);
    v += __shfl_xor_sync(0xffffffffu, v, 2);
    v += __shfl_xor_sync(0xffffffffu, v, 1);
    if (lane == 0) out[node] = v + bo[0];
}

// ---------------------------------------------------------------------------
extern "C" void kernel_launch(void* const* d_in, const int* in_sizes, int n_in,
                              void* d_out, int out_size)
{
    const float* x         = (const float*)d_in[0];
    const float* positions = (const float*)d_in[1];
    const float* W_in      = (const float*)d_in[2];
    const float* b_in      = (const float*)d_in[3];
    const float* Wg1       = (const float*)d_in[4];
    const float* bg1       = (const float*)d_in[5];
    const float* Wg2       = (const float*)d_in[6];
    const float* bg2       = (const float*)d_in[7];
    const float* Wm        = (const float*)d_in[8];
    const float* bm        = (const float*)d_in[9];
    const float* Wu        = (const float*)d_in[10];
    const float* bu        = (const float*)d_in[11];
    const float* Wp        = (const float*)d_in[12];
    const float* W_out     = (const float*)d_in[13];
    const float* b_out     = (const float*)d_in[14];
    const int*   edge      = (const int*)d_in[15];
    float* out = (float*)d_out;

    k_h0<<<BB, 256>>>(x, W_in, b_in);
    k_meand<<<NPTS, 256>>>(positions);
    k_geo<<<NPTS, 256>>>(Wg1, bg1, Wg2, bg2);
    k_init<<<NN, 256>>>(positions);

    const int* srcp = edge;
    const int* dstp = edge + NE;
    for (int l = 0; l < LAYERS; l++) {
        k_zero<<<592, 256>>>();
        msg_kernel<<<NE/TE, 256>>>(srcp, dstp,
                                   Wm + (size_t)l*513*HH, bm + l*HH, Wp + l*HH);
        upd_kernel<<<NN/TE, 256>>>(Wu + (size_t)l*512*HH, bu + l*HH);
    }
    k_out<<<NN/8, 256>>>(W_out, b_out, out);
}